// round 3
// baseline (speedup 1.0000x reference)
#include <cuda_runtime.h>
#include <cstdint>

// Problem constants: student/teacher [B=2, V=2, C=64, HW=1024], labels [2,2,1024]
#define N_TOT  4096   // B*V*HW
#define C_DIM  64
#define HW_DIM 1024
#define NIMG   2048   // V*HW  (only same-image pairs contribute)
#define RTILE  16     // anchor rows per block
#define JCHUNK 512    // columns per chunk (stays within one view: 512 <= 1024)
#define CSLICE 16     // c-slice per smem stage

// Scratch (device globals: no allocation allowed)
__device__ float g_sinv[N_TOT];
__device__ float g_tinv[N_TOT];
__device__ float g_mlpp[N_TOT];
__device__ float g_cnt[N_TOT];

// ---------- packed f32x2 helpers (Blackwell FFMA2 via PTX) ----------
__device__ __forceinline__ unsigned long long pack2(float lo, float hi) {
    unsigned long long r;
    asm("mov.b64 %0, {%1, %2};" : "=l"(r) : "f"(lo), "f"(hi));
    return r;
}
__device__ __forceinline__ void unpack2(unsigned long long v, float& lo, float& hi) {
    asm("mov.b64 {%0, %1}, %2;" : "=f"(lo), "=f"(hi) : "l"(v));
}
__device__ __forceinline__ unsigned long long ffma2(unsigned long long a,
                                                    unsigned long long b,
                                                    unsigned long long c) {
    unsigned long long d;
    asm("fma.rn.f32x2 %0, %1, %2, %3;" : "=l"(d) : "l"(a), "l"(b), "l"(c));
    return d;
}

// ---------- kernel 1: inverse L2 norms only (no staging/transpose) ----------
// grid (16, 2): y=0 -> student, y=1 -> teacher; 256 thr; n = bx*256+tid
__global__ __launch_bounds__(256) void scl_norms_kernel(
    const float* __restrict__ stu, const float* __restrict__ tea) {
    int n = blockIdx.x * 256 + threadIdx.x;
    const float* src = blockIdx.y ? tea : stu;
    float* dst = blockIdx.y ? g_tinv : g_sinv;
    const float* base = src + (size_t)(n >> 10) * C_DIM * HW_DIM + (n & (HW_DIM - 1));
    float ss = 0.f;
#pragma unroll 8
    for (int c = 0; c < C_DIM; c++) {
        float v = base[c * HW_DIM];
        ss += v * v;
    }
    dst[n] = 1.f / fmaxf(sqrtf(ss), 1e-12f);
}

// ---------- kernel 2: fused register-tiled GEMM + masked log-softmax ----------
// Block: 16 rows x 2048 cols (4 chunks of 512). Thread tile: 4 rows x 8 cols.
// tid -> cg = tid & 63 (col group of 8), rg = tid >> 6 (row group of 4).
__global__ __launch_bounds__(256) void scl_main_kernel(
    const float* __restrict__ stu, const float* __restrict__ tea,
    const int* __restrict__ labels) {
    __shared__ __align__(16) float ts_s[CSLICE][JCHUNK];   // teacher slice (raw)
    __shared__ __align__(16) float sf_s[C_DIM][RTILE];     // student tile (pre-scaled)
    __shared__ int   lab_s[RTILE];
    __shared__ float redZ[8][4], redS[8][4], redC[8][4];

    int tid = threadIdx.x;
    int cg  = tid & 63;           // col group: cols cg*8 .. cg*8+7 within chunk
    int rg  = tid >> 6;           // row group: rows rg*4 .. rg*4+3
    int i0  = blockIdx.x * RTILE;
    int bv_i = i0 >> 10;
    int p_i  = i0 & (HW_DIM - 1);
    int jbase = i0 & ~(NIMG - 1);

    // stage student tile (sinv folded in): sf_s[c][r]
    for (int idx = tid; idx < C_DIM * RTILE; idx += 256) {
        int c = idx >> 4, r = idx & (RTILE - 1);
        sf_s[c][r] = stu[(size_t)bv_i * C_DIM * HW_DIM + c * HW_DIM + p_i + r] *
                     g_sinv[i0 + r];
    }
    if (tid < RTILE) lab_s[tid] = labels[i0 + tid];

    float Z[4], S[4], CT[4];
#pragma unroll
    for (int r = 0; r < 4; r++) { Z[r] = 0.f; S[r] = 0.f; CT[r] = 0.f; }

    for (int chunk = 0; chunk < NIMG / JCHUNK; chunk++) {
        int jchunk = jbase + chunk * JCHUNK;        // global col of chunk start
        int bv_j = jchunk >> 10;
        int p_j  = jchunk & (HW_DIM - 1);
        const float* tbase = tea + (size_t)bv_j * C_DIM * HW_DIM + p_j;

        // accumulators: acc[rr][cp] = f32x2 over col pair (2cp, 2cp+1)
        unsigned long long acc[4][4];
#pragma unroll
        for (int rr = 0; rr < 4; rr++)
#pragma unroll
            for (int cp = 0; cp < 4; cp++) acc[rr][cp] = 0ull;

        for (int cs = 0; cs < C_DIM / CSLICE; cs++) {
            __syncthreads();
            // stage teacher slice: ts_s[cr][q], float4 loads, coalesced
            {
                const float4* src4 = (const float4*)(tbase + (cs * CSLICE) * HW_DIM);
                float4* dst4 = (float4*)&ts_s[0][0];
                // each thread: 8 float4 (16 rows x 128 float4/row / 256 thr)
#pragma unroll
                for (int k = 0; k < 8; k++) {
                    int e = k * 256 + tid;            // float4 index in slice
                    int cr = e >> 7;                  // /128
                    int q4 = e & 127;
                    dst4[cr * (JCHUNK / 4) + q4] = src4[cr * (HW_DIM / 4) + q4];
                }
            }
            __syncthreads();

#pragma unroll 8
            for (int cr = 0; cr < CSLICE; cr++) {
                int c = cs * CSLICE + cr;
                // teacher: 8 cols as two float4 -> four aligned f32x2 pairs
                float4 t03 = *(const float4*)&ts_s[cr][cg * 8];
                float4 t47 = *(const float4*)&ts_s[cr][cg * 8 + 4];
                unsigned long long tp[4];
                tp[0] = pack2(t03.x, t03.y);
                tp[1] = pack2(t03.z, t03.w);
                tp[2] = pack2(t47.x, t47.y);
                tp[3] = pack2(t47.z, t47.w);
#pragma unroll
                for (int rr = 0; rr < 4; rr++) {
                    float s = sf_s[c][rg * 4 + rr];   // LDS.32 broadcast
                    unsigned long long sp = pack2(s, s);
#pragma unroll
                    for (int cp = 0; cp < 4; cp++)
                        acc[rr][cp] = ffma2(sp, tp[cp], acc[rr][cp]);
                }
            }
        }

        // epilogue for this chunk: 4 rows x 8 cols of raw dots
        int j0 = jchunk + cg * 8;
#pragma unroll
        for (int cp = 0; cp < 4; cp++) {
#pragma unroll
            for (int half = 0; half < 2; half++) {
                int cc = cp * 2 + half;
                int j = j0 + cc;
                float tin10 = g_tinv[j] * 10.f;       // fold 1/T
                int lj = labels[j];
#pragma unroll
                for (int rr = 0; rr < 4; rr++) {
                    float dlo, dhi;
                    unpack2(acc[rr][cp], dlo, dhi);
                    float d = half ? dhi : dlo;
                    float l = d * tin10;              // logit in [-10,10]
                    float e = __expf(l - 10.f);       // fixed shift M=10
                    int r = rg * 4 + rr;
                    if (j != i0 + r) {
                        Z[rr] += e;
                        if (lj == lab_s[r]) { S[rr] += l; CT[rr] += 1.f; }
                    }
                }
            }
        }
    }

    // deterministic reduction: all 32 lanes of a warp share rg
#pragma unroll
    for (int rr = 0; rr < 4; rr++) {
#pragma unroll
        for (int off = 16; off > 0; off >>= 1) {
            Z[rr]  += __shfl_down_sync(0xffffffffu, Z[rr],  off);
            S[rr]  += __shfl_down_sync(0xffffffffu, S[rr],  off);
            CT[rr] += __shfl_down_sync(0xffffffffu, CT[rr], off);
        }
    }
    int warp = tid >> 5, lane = tid & 31;
    if (lane == 0) {
#pragma unroll
        for (int rr = 0; rr < 4; rr++) {
            redZ[warp][rr] = Z[rr]; redS[warp][rr] = S[rr]; redC[warp][rr] = CT[rr];
        }
    }
    __syncthreads();
    if (tid < RTILE) {
        int r = tid, g = r >> 2, rr = r & 3;         // warps 2g, 2g+1 hold row r
        float z  = redZ[2 * g][rr] + redZ[2 * g + 1][rr];
        float s  = redS[2 * g][rr] + redS[2 * g + 1][rr];
        float ct = redC[2 * g][rr] + redC[2 * g + 1][rr];
        g_mlpp[i0 + r] = (s - ct * (10.f + logf(z))) / (ct + 1e-8f);
        g_cnt[i0 + r]  = ct;
    }
}

// ---------- kernel 3: deterministic final reduction ----------
__global__ __launch_bounds__(256) void scl_finalize_kernel(
    const int* __restrict__ labels, float* __restrict__ out) {
    __shared__ float rt[256], rv[256], rb[256];
    int tid = threadIdx.x;
    float t = 0.f, nv = 0.f, nbv = 0.f;
    for (int i = tid; i < N_TOT; i += 256) {
        float ct = g_cnt[i];
        if (ct > 0.5f) {                 // valid: numerator_sums > eps
            t  += g_mlpp[i];
            nv += 1.f;
            if (labels[i] != 0) nbv += 1.f;
        }
    }
    rt[tid] = t; rv[tid] = nv; rb[tid] = nbv;
    __syncthreads();
    for (int s = 128; s > 0; s >>= 1) {
        if (tid < s) { rt[tid] += rt[tid + s]; rv[tid] += rv[tid + s]; rb[tid] += rb[tid + s]; }
        __syncthreads();
    }
    if (tid == 0) {
        float loss = -rt[0] / rv[0];
        out[0] = loss * rb[0] / (rb[0] + 1e-8f);   // bg_anchors=False rescale
    }
}

extern "C" void kernel_launch(void* const* d_in, const int* in_sizes, int n_in,
                              void* d_out, int out_size) {
    const float* stu    = (const float*)d_in[0];
    const float* tea    = (const float*)d_in[1];
    const int*   labels = (const int*)d_in[2];
    float* out = (float*)d_out;

    dim3 ngrid(N_TOT / 256, 2);
    scl_norms_kernel<<<ngrid, 256>>>(stu, tea);
    scl_main_kernel<<<N_TOT / RTILE, 256>>>(stu, tea, labels);
    scl_finalize_kernel<<<1, 256>>>(labels, out);
}

// round 5
// speedup vs baseline: 1.0141x; 1.0141x over previous
#include <cuda_runtime.h>
#include <cstdint>

// Problem constants: student/teacher [B=2, V=2, C=64, HW=1024], labels [2,2,1024]
#define N_TOT  4096   // B*V*HW
#define C_DIM  64
#define HW_DIM 1024
#define NIMG   2048   // V*HW  (only same-image pairs contribute)
#define RTILE  16     // anchor rows per block
#define JCHUNK 512    // columns per chunk (within one view)
#define CSLICE 8      // c-rows staged per smem slice

// Scratch (device globals: no allocation allowed)
__device__ float g_mlpp[N_TOT];
__device__ float g_cnt[N_TOT];

// ---------- packed f32x2 helpers (Blackwell FFMA2 via PTX) ----------
__device__ __forceinline__ unsigned long long pack2(float lo, float hi) {
    unsigned long long r;
    asm("mov.b64 %0, {%1, %2};" : "=l"(r) : "f"(lo), "f"(hi));
    return r;
}
__device__ __forceinline__ void unpack2(unsigned long long v, float& lo, float& hi) {
    asm("mov.b64 {%0, %1}, %2;" : "=f"(lo), "=f"(hi) : "l"(v));
}
__device__ __forceinline__ unsigned long long ffma2(unsigned long long a,
                                                    unsigned long long b,
                                                    unsigned long long c) {
    unsigned long long d;
    asm("fma.rn.f32x2 %0, %1, %2, %3;" : "=l"(d) : "l"(a), "l"(b), "l"(c));
    return d;
}

// ---------- fused kernel: GEMM + norms + masked log-softmax ----------
// Block = 16 anchor rows x 2048 cols (4 chunks of 512). Thread tile 4x8.
// tid: cg = tid & 63 (8-col group), rg = tid >> 6 (4-row group).
__global__ __launch_bounds__(256) void scl_main_kernel(
    const float* __restrict__ stu, const float* __restrict__ tea,
    const int* __restrict__ labels) {
    __shared__ __align__(16) float ts_s[CSLICE][JCHUNK];          // raw teacher slice
    __shared__ __align__(16) unsigned long long sf2_s[C_DIM][RTILE]; // student dup-pairs
    __shared__ float sinv_s[RTILE];
    __shared__ int   lab_s[RTILE];
    __shared__ float redZ[8][4], redS[8][4], redC[8][4];

    int tid = threadIdx.x;
    int cg  = tid & 63;
    int rg  = tid >> 6;
    int i0  = blockIdx.x * RTILE;
    int bv_i = i0 >> 10;
    int p_i  = i0 & (HW_DIM - 1);
    int jbase = i0 & ~(NIMG - 1);

    // --- stage student tile as duplicated f32x2 pairs ---
    {
        const float* sb = stu + (size_t)bv_i * C_DIM * HW_DIM + p_i;
#pragma unroll
        for (int k = 0; k < 4; k++) {
            int idx = k * 256 + tid;          // 0..1023
            int c = idx >> 4, r = idx & (RTILE - 1);
            float v = sb[c * HW_DIM + r];
            sf2_s[c][r] = pack2(v, v);
        }
    }
    if (tid < RTILE) lab_s[tid] = labels[i0 + tid];
    __syncthreads();
    // student inverse norms (16 threads, reads staged tile)
    if (tid < RTILE) {
        float ss = 0.f;
#pragma unroll
        for (int c = 0; c < C_DIM; c++) {
            float lo, hi;
            unpack2(sf2_s[c][tid], lo, hi);
            ss += lo * lo;
        }
        sinv_s[tid] = rsqrtf(fmaxf(ss, 1e-24f));
    }
    // (visibility of sinv_s guaranteed by syncthreads inside the slice loop
    //  before any epilogue read)

    float Z[4], S[4], CT[4];
#pragma unroll
    for (int r = 0; r < 4; r++) { Z[r] = 0.f; S[r] = 0.f; CT[r] = 0.f; }

    // staging addressing: element e = k*256+tid -> cr = e>>7, q4 = e&127
    int st_cr = 0, st_q4 = 0;  // per-k computed inline below

    for (int chunk = 0; chunk < NIMG / JCHUNK; chunk++) {
        int jchunk = jbase + chunk * JCHUNK;
        int bv_j = jchunk >> 10;
        int p_j  = jchunk & (HW_DIM - 1);
        const float* tbase = tea + (size_t)bv_j * C_DIM * HW_DIM + p_j;

        unsigned long long acc[4][4];   // acc[rr][cp]
        unsigned long long tss[4];      // teacher col sumsq (f32x2 per col pair)
#pragma unroll
        for (int rr = 0; rr < 4; rr++)
#pragma unroll
            for (int cp = 0; cp < 4; cp++) acc[rr][cp] = 0ull;
#pragma unroll
        for (int cp = 0; cp < 4; cp++) tss[cp] = 0ull;

        // prologue: prefetch slice 0 of this chunk into registers
        float4 pf[4];
#pragma unroll
        for (int k = 0; k < 4; k++) {
            int e = k * 256 + tid;
            int cr = e >> 7, q4 = e & 127;
            pf[k] = *(const float4*)(tbase + cr * HW_DIM + q4 * 4);
        }

        for (int cs = 0; cs < C_DIM / CSLICE; cs++) {
            __syncthreads();   // previous compute done reading ts_s
#pragma unroll
            for (int k = 0; k < 4; k++) {
                int e = k * 256 + tid;
                int cr = e >> 7, q4 = e & 127;
                *(float4*)&ts_s[cr][q4 * 4] = pf[k];
            }
            __syncthreads();
            if (cs < C_DIM / CSLICE - 1) {
                const float* nbase = tbase + (cs + 1) * CSLICE * HW_DIM;
#pragma unroll
                for (int k = 0; k < 4; k++) {
                    int e = k * 256 + tid;
                    int cr = e >> 7, q4 = e & 127;
                    pf[k] = *(const float4*)(nbase + cr * HW_DIM + q4 * 4);
                }
            }

#pragma unroll
            for (int cr = 0; cr < CSLICE; cr++) {
                int c = cs * CSLICE + cr;
                // two LDS.128 -> four f32x2 teacher operands, no packing
                ulonglong2 tA = *(const ulonglong2*)&ts_s[cr][cg * 8];
                ulonglong2 tB = *(const ulonglong2*)&ts_s[cr][cg * 8 + 4];
                tss[0] = ffma2(tA.x, tA.x, tss[0]);
                tss[1] = ffma2(tA.y, tA.y, tss[1]);
                tss[2] = ffma2(tB.x, tB.x, tss[2]);
                tss[3] = ffma2(tB.y, tB.y, tss[3]);
#pragma unroll
                for (int rr = 0; rr < 4; rr++) {
                    unsigned long long sp = sf2_s[c][rg * 4 + rr];  // LDS.64 dup pair
                    acc[rr][0] = ffma2(sp, tA.x, acc[rr][0]);
                    acc[rr][1] = ffma2(sp, tA.y, acc[rr][1]);
                    acc[rr][2] = ffma2(sp, tB.x, acc[rr][2]);
                    acc[rr][3] = ffma2(sp, tB.y, acc[rr][3]);
                }
            }
        }

        // epilogue: 8 cols x 4 rows
        int j0 = jchunk + cg * 8;
#pragma unroll
        for (int cp = 0; cp < 4; cp++) {
            float ss0, ss1;
            unpack2(tss[cp], ss0, ss1);
#pragma unroll
            for (int half = 0; half < 2; half++) {
                int j = j0 + cp * 2 + half;
                float tinv10 = rsqrtf(fmaxf(half ? ss1 : ss0, 1e-24f)) * 10.f;
                int lj = labels[j];
#pragma unroll
                for (int rr = 0; rr < 4; rr++) {
                    float dlo, dhi;
                    unpack2(acc[rr][cp], dlo, dhi);
                    float d = half ? dhi : dlo;
                    int r = rg * 4 + rr;
                    float l = d * tinv10 * sinv_s[r];   // logit in [-10,10]
                    float e = __expf(l - 10.f);         // fixed shift M=10
                    if (j != i0 + r) {
                        Z[rr] += e;
                        if (lj == lab_s[r]) { S[rr] += l; CT[rr] += 1.f; }
                    }
                }
            }
        }
    }

    // deterministic reduction (all lanes of a warp share rg)
#pragma unroll
    for (int rr = 0; rr < 4; rr++) {
#pragma unroll
        for (int off = 16; off > 0; off >>= 1) {
            Z[rr]  += __shfl_down_sync(0xffffffffu, Z[rr],  off);
            S[rr]  += __shfl_down_sync(0xffffffffu, S[rr],  off);
            CT[rr] += __shfl_down_sync(0xffffffffu, CT[rr], off);
        }
    }
    int warp = tid >> 5, lane = tid & 31;
    if (lane == 0) {
#pragma unroll
        for (int rr = 0; rr < 4; rr++) {
            redZ[warp][rr] = Z[rr]; redS[warp][rr] = S[rr]; redC[warp][rr] = CT[rr];
        }
    }
    __syncthreads();
    if (tid < RTILE) {
        int r = tid, g = r >> 2, rr = r & 3;     // warps 2g, 2g+1 hold row r
        float z  = redZ[2 * g][rr] + redZ[2 * g + 1][rr];
        float s  = redS[2 * g][rr] + redS[2 * g + 1][rr];
        float ct = redC[2 * g][rr] + redC[2 * g + 1][rr];
        g_mlpp[i0 + r] = (s - ct * (10.f + logf(z))) / (ct + 1e-8f);
        g_cnt[i0 + r]  = ct;
    }
}

// ---------- final deterministic reduction ----------
__global__ __launch_bounds__(256) void scl_finalize_kernel(
    const int* __restrict__ labels, float* __restrict__ out) {
    __shared__ float rt[256], rv[256], rb[256];
    int tid = threadIdx.x;
    float t = 0.f, nv = 0.f, nbv = 0.f;
    for (int i = tid; i < N_TOT; i += 256) {
        float ct = g_cnt[i];
        if (ct > 0.5f) {                 // valid: numerator_sums > eps
            t  += g_mlpp[i];
            nv += 1.f;
            if (labels[i] != 0) nbv += 1.f;
        }
    }
    rt[tid] = t; rv[tid] = nv; rb[tid] = nbv;
    __syncthreads();
    for (int s = 128; s > 0; s >>= 1) {
        if (tid < s) { rt[tid] += rt[tid + s]; rv[tid] += rv[tid + s]; rb[tid] += rb[tid + s]; }
        __syncthreads();
    }
    if (tid == 0) {
        float loss = -rt[0] / rv[0];
        out[0] = loss * rb[0] / (rb[0] + 1e-8f);   // bg_anchors=False rescale
    }
}

extern "C" void kernel_launch(void* const* d_in, const int* in_sizes, int n_in,
                              void* d_out, int out_size) {
    const float* stu    = (const float*)d_in[0];
    const float* tea    = (const float*)d_in[1];
    const int*   labels = (const int*)d_in[2];
    float* out = (float*)d_out;

    scl_main_kernel<<<N_TOT / RTILE, 256>>>(stu, tea, labels);
    scl_finalize_kernel<<<1, 256>>>(labels, out);
}